// round 12
// baseline (speedup 1.0000x reference)
#include <cuda_runtime.h>
#include <math.h>

#define BT 4096
#define CLIPF 0.2f

// ------------------------------ scratch ------------------------------------
__device__ float  g_feat[BT * 256];
__device__ float  g_xz[BT * 1024];
__device__ float  g_hbuf[2 * 64 * 256];
__device__ float  g_lstm[BT * 256];
__device__ float  g_lg_pir[BT];
__device__ float  g_lg_pim[BT];
__device__ float  g_vpred[BT];
__device__ double g_ent_pir[BT];
__device__ double g_ent_pim[BT];
__device__ double g_vf_row[BT];

__device__ unsigned int g_bar_cnt = 0u;
__device__ unsigned int g_bar_gen = 0u;

// Zero barrier state every launch (deterministic across graph replays).
__global__ void init_kernel() {
    g_bar_cnt = 0u;
    g_bar_gen = 0u;
}

// Grid barrier, generation-targeted, release/acquire (no membar, no L1 flush).
__device__ __forceinline__ void grid_barrier_step(unsigned int nblocks,
                                                  unsigned int next_gen) {
    __syncthreads();
    if (threadIdx.x == 0) {
        if (blockIdx.x == 0) {
            unsigned int c;
            do {
                asm volatile("ld.acquire.gpu.global.u32 %0, [%1];"
                             : "=r"(c) : "l"(&g_bar_cnt) : "memory");
            } while (c != nblocks - 1u);
            asm volatile("st.global.u32 [%0], %1;"
                         :: "l"(&g_bar_cnt), "r"(0u) : "memory");
            asm volatile("st.release.gpu.global.u32 [%0], %1;"
                         :: "l"(&g_bar_gen), "r"(next_gen) : "memory");
        } else {
            asm volatile("red.release.gpu.global.add.u32 [%0], %1;"
                         :: "l"(&g_bar_cnt), "r"(1u) : "memory");
            unsigned int ggen;
            do {
                asm volatile("ld.acquire.gpu.global.u32 %0, [%1];"
                             : "=r"(ggen) : "l"(&g_bar_gen) : "memory");
            } while (ggen != next_gen);
        }
    }
    __syncthreads();
}

__device__ __forceinline__ float leaky(float v) { return v > 0.f ? v : 0.2f * v; }
__device__ __forceinline__ float sigm(float v)  { return 1.f / (1.f + expf(-v)); }

// ------------------------------ conv stack ---------------------------------
__global__ __launch_bounds__(256) void conv_kernel(
    const float* __restrict__ x,
    const float* __restrict__ W1, const float* __restrict__ b1,
    const float* __restrict__ W2, const float* __restrict__ b2,
    const float* __restrict__ W3, const float* __restrict__ b3,
    const float* __restrict__ W4, const float* __restrict__ b4)
{
    __shared__ float w1[512], w2[2048];
    __shared__ float sb1[16], sb2[32], sb3[64], sb4[128];
    __shared__ float sin_[832], a1[384], a2[480], a3[128];
    const int tid = threadIdx.x;
    for (int i = tid; i < 512;  i += 256) w1[i] = W1[i];
    for (int i = tid; i < 2048; i += 256) w2[i] = W2[i];
    if (tid < 16)  sb1[tid] = b1[tid];
    if (tid < 32)  sb2[tid] = b2[tid];
    if (tid < 64)  sb3[tid] = b3[tid];
    if (tid < 128) sb4[tid] = b4[tid];

    for (int s = 0; s < 8; s++) {
        const int bt = blockIdx.x * 8 + s;
        __syncthreads();
        for (int i = tid; i < 832; i += 256) sin_[i] = x[(size_t)bt * 832 + i];
        __syncthreads();
        // conv1: (13,8,8)->(6,4,16) k2 s2
        for (int o = tid; o < 384; o += 256) {
            int oh = o >> 6, rem = o & 63, ow = rem >> 4, co = rem & 15;
            float acc = sb1[co];
#pragma unroll
            for (int kh = 0; kh < 2; kh++)
#pragma unroll
                for (int kw = 0; kw < 2; kw++)
#pragma unroll
                    for (int ci = 0; ci < 8; ci++)
                        acc = fmaf(sin_[(oh*2+kh)*64 + (ow*2+kw)*8 + ci],
                                   w1[((kh*2+kw)*8 + ci)*16 + co], acc);
            a1[o] = leaky(acc);
        }
        __syncthreads();
        // conv2: (6,4,16)->(5,3,32) k2 s1
        for (int o = tid; o < 480; o += 256) {
            int oh = o / 96, r2 = o % 96, ow = r2 >> 5, co = r2 & 31;
            float acc = sb2[co];
#pragma unroll
            for (int kh = 0; kh < 2; kh++)
#pragma unroll
                for (int kw = 0; kw < 2; kw++)
#pragma unroll
                    for (int ci = 0; ci < 16; ci++)
                        acc = fmaf(a1[(oh+kh)*64 + (ow+kw)*16 + ci],
                                   w2[((kh*2+kw)*16 + ci)*32 + co], acc);
            a2[o] = leaky(acc);
        }
        __syncthreads();
        // conv3: (5,3,32)->(2,1,64) k2 s2
        for (int o = tid; o < 128; o += 256) {
            int oh = o >> 6, co = o & 63;
            float acc = sb3[co];
#pragma unroll
            for (int kh = 0; kh < 2; kh++)
#pragma unroll
                for (int kw = 0; kw < 2; kw++)
#pragma unroll 8
                    for (int ci = 0; ci < 32; ci++)
                        acc = fmaf(a2[(oh*2+kh)*96 + kw*32 + ci],
                                   __ldg(&W3[((kh*2+kw)*32 + ci)*64 + co]), acc);
            a3[o] = leaky(acc);
        }
        __syncthreads();
        // conv4 1x1 -> (2,1,128); channels_first flatten: feat[c*2 + oh]
        {
            int o = tid, oh = o >> 7, co = o & 127;
            float acc = sb4[co];
#pragma unroll 8
            for (int ci = 0; ci < 64; ci++)
                acc = fmaf(a3[oh*64 + ci], __ldg(&W4[ci*128 + co]), acc);
            g_feat[(size_t)bt * 256 + co*2 + oh] = leaky(acc);
        }
    }
}

// ------------------------------ xz = feat @ Wk + b --------------------------
__global__ __launch_bounds__(128) void xz_kernel(const float* __restrict__ Wk,
                                                 const float* __restrict__ lb)
{
    __shared__ float a_sm[8][256];
    const int tid = threadIdx.x;
    const int r0 = blockIdx.y * 8;
    for (int i = tid; i < 8 * 256; i += 128)
        a_sm[i >> 8][i & 255] = g_feat[(size_t)(r0 + (i >> 8)) * 256 + (i & 255)];
    __syncthreads();

    const int j0 = blockIdx.x * 512 + tid * 4;
    float acc[8][4];
#pragma unroll
    for (int r = 0; r < 8; r++) { acc[r][0]=0.f; acc[r][1]=0.f; acc[r][2]=0.f; acc[r][3]=0.f; }

#pragma unroll 1
    for (int k = 0; k < 256; k += 4) {
        float4 w0 = __ldg((const float4*)(Wk + (size_t)(k+0)*1024 + j0));
        float4 w1 = __ldg((const float4*)(Wk + (size_t)(k+1)*1024 + j0));
        float4 w2 = __ldg((const float4*)(Wk + (size_t)(k+2)*1024 + j0));
        float4 w3 = __ldg((const float4*)(Wk + (size_t)(k+3)*1024 + j0));
#pragma unroll
        for (int r = 0; r < 8; r++) {
            float4 a = *(const float4*)&a_sm[r][k];
            acc[r][0] = fmaf(a.w,w3.x,fmaf(a.z,w2.x,fmaf(a.y,w1.x,fmaf(a.x,w0.x,acc[r][0]))));
            acc[r][1] = fmaf(a.w,w3.y,fmaf(a.z,w2.y,fmaf(a.y,w1.y,fmaf(a.x,w0.y,acc[r][1]))));
            acc[r][2] = fmaf(a.w,w3.z,fmaf(a.z,w2.z,fmaf(a.y,w1.z,fmaf(a.x,w0.z,acc[r][2]))));
            acc[r][3] = fmaf(a.w,w3.w,fmaf(a.z,w2.w,fmaf(a.y,w1.w,fmaf(a.x,w0.w,acc[r][3]))));
        }
    }
    float4 bv = *(const float4*)(lb + j0);
#pragma unroll
    for (int r = 0; r < 8; r++) {
        float4 o; o.x=acc[r][0]+bv.x; o.y=acc[r][1]+bv.y; o.z=acc[r][2]+bv.z; o.w=acc[r][3]+bv.w;
        *(float4*)&g_xz[(size_t)(r0 + r) * 1024 + j0] = o;
    }
}

// ------------------------------ LSTM (persistent, 128 x 512) -----------------
// 16 warps/SM (vs 8): each 256-wide dot product is split across a thread PAIR
// (half = tid&1, k-range 128 each, combined by one shfl_xor). Four independent
// accumulators per output pair break the FFMA dependency chains. h(t-1) staged
// to smem once per block per step (coalesced float4, MLP=8/thread).
__global__ __launch_bounds__(512) void lstm_kernel(const float* __restrict__ Wr)
{
    extern __shared__ float hstage[];    // 64 x 256 floats = 64 KB
    __shared__ float w_sm[8][256];       // [gate*2+unit][k]
    __shared__ float z_sm[64][4][2];
    __shared__ float c_sm[64][2];
    const int tid = threadIdx.x;
    const int j0 = blockIdx.x * 2;

    for (int i = tid; i < 2048; i += 512) {
        int col = i >> 8, k = i & 255, gg = col >> 1, u = col & 1;
        w_sm[col][k] = Wr[(size_t)k * 1024 + gg * 256 + j0 + u];
    }
    if (tid < 128) c_sm[tid >> 1][tid & 1] = 0.f;
    __syncthreads();

    const int half = tid & 1;        // k-range selector within pair
    const int idx  = tid >> 1;       // 0..255
    const int b    = idx >> 2;       // batch 0..63
    const int g    = idx & 3;        // gate 0..3

    const float* wa = w_sm[g * 2 + 0] + half * 128;
    const float* wb = w_sm[g * 2 + 1] + half * 128;
    const float* hp = hstage + b * 256 + half * 128;

    for (int t = 0; t < 64; t++) {
        if (t > 0) {
            const float4* src = (const float4*)(g_hbuf + ((t - 1) & 1) * (64 * 256));
            float4* dst = (float4*)hstage;
#pragma unroll
            for (int i = 0; i < 8; i++)
                dst[tid + i * 512] = __ldcg(src + tid + i * 512);
            __syncthreads();
        }
        float ax = 0.f, ay = 0.f, bx = 0.f, by = 0.f;
        if (t > 0) {
#pragma unroll
            for (int k = 0; k < 128; k += 4) {
                float4 h4 = *(const float4*)(hp + k);
                float4 wA = *(const float4*)(wa + k);
                float4 wB = *(const float4*)(wb + k);
                ax = fmaf(h4.x, wA.x, ax); ay = fmaf(h4.y, wA.y, ay);
                bx = fmaf(h4.x, wB.x, bx); by = fmaf(h4.y, wB.y, by);
                ax = fmaf(h4.z, wA.z, ax); ay = fmaf(h4.w, wA.w, ay);
                bx = fmaf(h4.z, wB.z, bx); by = fmaf(h4.w, wB.w, by);
            }
        }
        float acc0 = ax + ay;
        float acc1 = bx + by;
        acc0 += __shfl_xor_sync(0xffffffffu, acc0, 1);
        acc1 += __shfl_xor_sync(0xffffffffu, acc1, 1);
        if (half == 0) {
            const size_t row = (size_t)(b * 64 + t);
            z_sm[b][g][0] = acc0 + g_xz[row * 1024 + g * 256 + j0];
            z_sm[b][g][1] = acc1 + g_xz[row * 1024 + g * 256 + j0 + 1];
        }
        __syncthreads();
        if (tid < 128) {
            int b2 = tid >> 1, u = tid & 1;
            float zi = z_sm[b2][0][u], zf = z_sm[b2][1][u];
            float zg = z_sm[b2][2][u], zo = z_sm[b2][3][u];
            float c = sigm(zf) * c_sm[b2][u] + sigm(zi) * tanhf(zg);
            float hv = sigm(zo) * tanhf(c);
            c_sm[b2][u] = c;
            __stcg(&g_hbuf[(t & 1) * (64 * 256) + b2 * 256 + j0 + u], hv);
            g_lstm[(size_t)(b2 * 64 + t) * 256 + j0 + u] = hv;
        }
        grid_barrier_step(gridDim.x, (unsigned int)(t + 1));
    }
}

// ------------------------------ pir head + vpred (smem-staged) ---------------
__global__ __launch_bounds__(256) void pir_v_kernel(
    const float* __restrict__ pirW, const float* __restrict__ pirb,
    const float* __restrict__ vW,  const float* __restrict__ vb,
    const int* __restrict__ a_taken)
{
    __shared__ float ws[256 * 36];
    __shared__ float vws[256];
    __shared__ float hs[8][256];
    const int tid = threadIdx.x, warp = tid >> 5, lane = tid & 31;
    const int r0 = blockIdx.x * 8;

    for (int i = tid; i < 9216; i += 256) ws[i] = pirW[i];
    vws[tid] = vW[tid];
    for (int i = tid; i < 2048; i += 256)
        hs[i >> 8][i & 255] = g_lstm[(size_t)(r0 + (i >> 8)) * 256 + (i & 255)];
    __syncthreads();

    const int i = r0 + warp;
    float acc0 = 0.f, acc1 = 0.f, accv = 0.f;
#pragma unroll 4
    for (int k = 0; k < 256; k++) {
        float hk = hs[warp][k];
        acc0 = fmaf(hk, ws[k * 36 + lane], acc0);
        if (lane < 4) acc1 = fmaf(hk, ws[k * 36 + 32 + lane], acc1);
    }
    for (int k = lane; k < 256; k += 32) accv = fmaf(hs[warp][k], vws[k], accv);

    float l0 = acc0 + __ldg(&pirb[lane]);
    float l1 = (lane < 4) ? acc1 + __ldg(&pirb[lane + 32]) : 0.f;
    float e0 = expf(l0);
    float e1 = (lane < 4) ? expf(l1) : 0.f;
    float cs = e0 + e1;
    float ct = e0 * l0 + ((lane < 4) ? e1 * l1 : 0.f);
#pragma unroll
    for (int o = 16; o > 0; o >>= 1) {
        cs   += __shfl_down_sync(0xffffffffu, cs, o);
        ct   += __shfl_down_sync(0xffffffffu, ct, o);
        accv += __shfl_down_sync(0xffffffffu, accv, o);
    }
    float S = __shfl_sync(0xffffffffu, cs, 0);
    int a = a_taken[i];
    float laA = __shfl_sync(0xffffffffu, l0, a & 31);
    float laB = __shfl_sync(0xffffffffu, l1, a & 31);
    float la = (a < 32) ? laA : laB;
    if (lane == 0) {
        double lS = log((double)S);
        g_ent_pir[i] = (double)ct / (double)S - lS;   // sum p*log p
        g_lg_pir[i]  = (float)((double)la - lS);
        g_vpred[i]   = accv + vb[0];
    }
}

// ------------------------------ pim GEMM + fused epilogue --------------------
__global__ __launch_bounds__(256) void pim_kernel(
    const float* __restrict__ pimW, const float* __restrict__ pimb,
    const int* __restrict__ mask, const int* __restrict__ a_taken)
{
    __shared__ float a_sm[16][256];
    __shared__ float redS[16][8], redT[16][8];
    __shared__ double sRun[16], tRun[16];
    __shared__ float la_sm[16];
    __shared__ int aidx[16];
    const int tid = threadIdx.x, lane = tid & 31, warp = tid >> 5;
    const int r0 = blockIdx.x * 16;

    for (int i = tid; i < 16 * 256; i += 256)
        a_sm[i >> 8][i & 255] = g_lstm[(size_t)(r0 + (i >> 8)) * 256 + (i & 255)];
    if (tid < 16) { sRun[tid] = 0.0; tRun[tid] = 0.0; aidx[tid] = a_taken[r0 + tid]; la_sm[tid] = 0.f; }
    __syncthreads();

#pragma unroll 1
    for (int tile = 0; tile < 4; tile++) {
        const int jb = tile * 1024 + tid * 4;
        const float* Wp = pimW + jb;
        float acc[16][4];
#pragma unroll
        for (int r = 0; r < 16; r++) { acc[r][0]=0.f; acc[r][1]=0.f; acc[r][2]=0.f; acc[r][3]=0.f; }
#pragma unroll 1
        for (int k = 0; k < 256; k += 4) {
            float4 w0 = __ldg((const float4*)(Wp + (size_t)(k+0)*4096));
            float4 w1 = __ldg((const float4*)(Wp + (size_t)(k+1)*4096));
            float4 w2 = __ldg((const float4*)(Wp + (size_t)(k+2)*4096));
            float4 w3 = __ldg((const float4*)(Wp + (size_t)(k+3)*4096));
#pragma unroll
            for (int r = 0; r < 16; r++) {
                float4 a = *(const float4*)&a_sm[r][k];
                acc[r][0] = fmaf(a.w,w3.x,fmaf(a.z,w2.x,fmaf(a.y,w1.x,fmaf(a.x,w0.x,acc[r][0]))));
                acc[r][1] = fmaf(a.w,w3.y,fmaf(a.z,w2.y,fmaf(a.y,w1.y,fmaf(a.x,w0.y,acc[r][1]))));
                acc[r][2] = fmaf(a.w,w3.z,fmaf(a.z,w2.z,fmaf(a.y,w1.z,fmaf(a.x,w0.z,acc[r][2]))));
                acc[r][3] = fmaf(a.w,w3.w,fmaf(a.z,w2.w,fmaf(a.y,w1.w,fmaf(a.x,w0.w,acc[r][3]))));
            }
        }
        float4 bv = __ldg((const float4*)(pimb + jb));
#pragma unroll 1
        for (int r = 0; r < 16; r++) {
            int4 m = *(const int4*)(mask + (size_t)(r0 + r) * 4096 + jb);
            float s = 0.f, t = 0.f, l;
            l = acc[r][0] + bv.x; if (m.x) { float e = expf(l); s += e; t += e * l; } if (jb + 0 == aidx[r]) la_sm[r] = l;
            l = acc[r][1] + bv.y; if (m.y) { float e = expf(l); s += e; t += e * l; } if (jb + 1 == aidx[r]) la_sm[r] = l;
            l = acc[r][2] + bv.z; if (m.z) { float e = expf(l); s += e; t += e * l; } if (jb + 2 == aidx[r]) la_sm[r] = l;
            l = acc[r][3] + bv.w; if (m.w) { float e = expf(l); s += e; t += e * l; } if (jb + 3 == aidx[r]) la_sm[r] = l;
#pragma unroll
            for (int o = 16; o > 0; o >>= 1) {
                s += __shfl_down_sync(0xffffffffu, s, o);
                t += __shfl_down_sync(0xffffffffu, t, o);
            }
            if (lane == 0) { redS[r][warp] = s; redT[r][warp] = t; }
        }
        __syncthreads();
        if (tid < 16) {
            double s = 0.0, t = 0.0;
#pragma unroll
            for (int w = 0; w < 8; w++) { s += (double)redS[tid][w]; t += (double)redT[tid][w]; }
            sRun[tid] += s; tRun[tid] += t;
        }
        __syncthreads();
    }
    if (tid < 16) {
        const int i = r0 + tid;
        double S = sRun[tid], T1 = tRun[tid];
        double lS = log(S);
        g_ent_pim[i] = T1 / S - lS;                      // sum_masked p*log p
        g_lg_pim[i]  = (float)((double)la_sm[tid] - lS); // log pim[i, a]
    }
}

// ------------------------------ vf broadcast (register-tiled) ----------------
__global__ __launch_bounds__(256) void vf_kernel(const float* __restrict__ ovp,
                                                 const float* __restrict__ ret)
{
    __shared__ float vp_s[8];
    __shared__ float part[8][257];
    const int tid = threadIdx.x, warp = tid >> 5, lane = tid & 31;
    const int r0 = blockIdx.x * 8;
    if (tid < 8) vp_s[tid] = g_vpred[r0 + tid];
    __syncthreads();

    float accr[8];
#pragma unroll
    for (int r = 0; r < 8; r++) accr[r] = 0.f;

#pragma unroll 1
    for (int c = 0; c < 4; c++) {
        const int j0 = c * 1024 + tid * 4;
        float4 rt4 = __ldg((const float4*)(ret + j0));
        float4 ov4 = __ldg((const float4*)(ovp + j0));
#pragma unroll
        for (int r = 0; r < 8; r++) {
            float vp = vp_s[r];
            float d, dc, t0, t1, t2, t3;
            d = vp - rt4.x; dc = ov4.x + fminf(fmaxf(vp - ov4.x, -CLIPF), CLIPF) - rt4.x; t0 = fmaxf(d*d, dc*dc);
            d = vp - rt4.y; dc = ov4.y + fminf(fmaxf(vp - ov4.y, -CLIPF), CLIPF) - rt4.y; t1 = fmaxf(d*d, dc*dc);
            d = vp - rt4.z; dc = ov4.z + fminf(fmaxf(vp - ov4.z, -CLIPF), CLIPF) - rt4.z; t2 = fmaxf(d*d, dc*dc);
            d = vp - rt4.w; dc = ov4.w + fminf(fmaxf(vp - ov4.w, -CLIPF), CLIPF) - rt4.w; t3 = fmaxf(d*d, dc*dc);
            accr[r] += (t0 + t1) + (t2 + t3);
        }
    }
#pragma unroll
    for (int r = 0; r < 8; r++) part[r][tid] = accr[r];
    __syncthreads();

    // warp w reduces row w (fixed order -> deterministic)
    double s = 0.0;
#pragma unroll
    for (int m = 0; m < 8; m++) s += (double)part[warp][m * 32 + lane];
#pragma unroll
    for (int o = 16; o > 0; o >>= 1) s += __shfl_down_sync(0xffffffffu, s, o);
    if (lane == 0) g_vf_row[r0 + warp] = s;
}

// ------------------------------ finalize ------------------------------------
__global__ __launch_bounds__(1024) void finalize_kernel(
    const float* __restrict__ GAE, const float* __restrict__ lgold, float* __restrict__ out)
{
    __shared__ double rA[1024], rB[1024];
    const int tid = threadIdx.x;
    double s1 = 0.0, s2 = 0.0;
    for (int i = tid; i < BT; i += 1024) { double g = GAE[i]; s1 += g; s2 += g * g; }
    rA[tid] = s1; rB[tid] = s2; __syncthreads();
    for (int o = 512; o > 0; o >>= 1) {
        if (tid < o) { rA[tid] += rA[tid + o]; rB[tid] += rB[tid + o]; }
        __syncthreads();
    }
    double mean = rA[0] / (double)BT;
    double var  = rB[0] / (double)BT - mean * mean;
    if (var < 0.0) var = 0.0;
    double denom = sqrt(var) + 1e-8;
    __syncthreads();

    double pg = 0.0, ent = 0.0, vf = 0.0;
    for (int i = tid; i < BT; i += 1024) {
        double g = ((double)GAE[i] - mean) / denom;
        float lgnew = ((i & 1) == 0) ? g_lg_pir[i] : g_lg_pim[i];
        double rt = exp((double)lgnew - (double)lgold[i]);
        double rtc = rt < (1.0 - CLIPF) ? (1.0 - CLIPF) : (rt > (1.0 + CLIPF) ? (1.0 + CLIPF) : rt);
        double p1 = -g * rt, p2 = -g * rtc;
        pg  += (p1 > p2) ? p1 : p2;
        ent += g_ent_pir[i] + g_ent_pim[i];
        vf  += g_vf_row[i];
    }
    rA[tid] = pg; rB[tid] = ent; __syncthreads();
    for (int o = 512; o > 0; o >>= 1) {
        if (tid < o) { rA[tid] += rA[tid + o]; rB[tid] += rB[tid + o]; }
        __syncthreads();
    }
    double pg_tot = rA[0], ent_tot = rB[0];
    __syncthreads();
    rA[tid] = vf; __syncthreads();
    for (int o = 512; o > 0; o >>= 1) {
        if (tid < o) rA[tid] += rA[tid + o];
        __syncthreads();
    }
    if (tid == 0) {
        double pg_loss = pg_tot / (double)BT;
        double entropy = -ent_tot;
        double vf_loss = 0.5 * rA[0] / ((double)BT * (double)BT);
        out[0] = (float)(pg_loss - entropy + vf_loss);
        out[1] = (float)pg_loss;
        out[2] = (float)entropy;
        out[3] = (float)vf_loss;
    }
}

// ------------------------------ launch --------------------------------------
extern "C" void kernel_launch(void* const* d_in, const int* in_sizes, int n_in,
                              void* d_out, int out_size) {
    const float* x      = (const float*)d_in[0];
    const int*   mask   = (const int*)  d_in[1];
    const float* lgold  = (const float*)d_in[2];
    const int*   ataken = (const int*)  d_in[3];
    const float* GAE    = (const float*)d_in[4];
    const float* ovp    = (const float*)d_in[5];
    const float* ret    = (const float*)d_in[6];
    const float* W1 = (const float*)d_in[7],  *b1 = (const float*)d_in[8];
    const float* W2 = (const float*)d_in[9],  *b2 = (const float*)d_in[10];
    const float* W3 = (const float*)d_in[11], *b3 = (const float*)d_in[12];
    const float* W4 = (const float*)d_in[13], *b4 = (const float*)d_in[14];
    const float* lk = (const float*)d_in[15];
    const float* lr = (const float*)d_in[16];
    const float* lb = (const float*)d_in[17];
    const float* pirW = (const float*)d_in[18], *pirb = (const float*)d_in[19];
    const float* pimW = (const float*)d_in[20], *pimb = (const float*)d_in[21];
    const float* vW   = (const float*)d_in[22], *vb   = (const float*)d_in[23];
    float* out = (float*)d_out;

    static int lstm_smem_set = 0;
    if (!lstm_smem_set) {
        cudaFuncSetAttribute(lstm_kernel,
                             cudaFuncAttributeMaxDynamicSharedMemorySize, 65536);
        lstm_smem_set = 1;
    }

    init_kernel<<<1, 1>>>();
    conv_kernel<<<512, 256>>>(x, W1, b1, W2, b2, W3, b3, W4, b4);
    xz_kernel<<<dim3(2, 512), 128>>>(lk, lb);
    lstm_kernel<<<128, 512, 65536>>>(lr);
    pir_v_kernel<<<512, 256>>>(pirW, pirb, vW, vb, ataken);
    pim_kernel<<<256, 256>>>(pimW, pimb, mask, ataken);
    vf_kernel<<<512, 256>>>(ovp, ret);
    finalize_kernel<<<1, 1024>>>(GAE, lgold, out);
}

// round 13
// speedup vs baseline: 2.0075x; 2.0075x over previous
#include <cuda_runtime.h>
#include <math.h>

#define BT 4096
#define CLIPF 0.2f
#define HPAD 260   // padded row stride (floats): 260 % 32 == 4, rows 16B-aligned

// ------------------------------ scratch ------------------------------------
__device__ float  g_feat[BT * 256];
__device__ float  g_xz[BT * 1024];
__device__ float  g_hbuf[2 * 64 * 256];
__device__ float  g_lstm[BT * 256];
__device__ float  g_lg_pir[BT];
__device__ float  g_lg_pim[BT];
__device__ float  g_vpred[BT];
__device__ double g_ent_pir[BT];
__device__ double g_ent_pim[BT];
__device__ double g_vf_row[BT];

__device__ unsigned int g_bar_cnt = 0u;
__device__ unsigned int g_bar_gen = 0u;

// Zero barrier state every launch (deterministic across graph replays).
__global__ void init_kernel() {
    g_bar_cnt = 0u;
    g_bar_gen = 0u;
}

// Grid barrier, generation-targeted, release/acquire (no membar, no L1 flush).
__device__ __forceinline__ void grid_barrier_step(unsigned int nblocks,
                                                  unsigned int next_gen) {
    __syncthreads();
    if (threadIdx.x == 0) {
        if (blockIdx.x == 0) {
            unsigned int c;
            do {
                asm volatile("ld.acquire.gpu.global.u32 %0, [%1];"
                             : "=r"(c) : "l"(&g_bar_cnt) : "memory");
            } while (c != nblocks - 1u);
            asm volatile("st.global.u32 [%0], %1;"
                         :: "l"(&g_bar_cnt), "r"(0u) : "memory");
            asm volatile("st.release.gpu.global.u32 [%0], %1;"
                         :: "l"(&g_bar_gen), "r"(next_gen) : "memory");
        } else {
            asm volatile("red.release.gpu.global.add.u32 [%0], %1;"
                         :: "l"(&g_bar_cnt), "r"(1u) : "memory");
            unsigned int ggen;
            do {
                asm volatile("ld.acquire.gpu.global.u32 %0, [%1];"
                             : "=r"(ggen) : "l"(&g_bar_gen) : "memory");
            } while (ggen != next_gen);
        }
    }
    __syncthreads();
}

__device__ __forceinline__ float leaky(float v) { return v > 0.f ? v : 0.2f * v; }
__device__ __forceinline__ float sigm(float v)  { return 1.f / (1.f + expf(-v)); }

// ------------------------------ conv stack ---------------------------------
__global__ __launch_bounds__(256) void conv_kernel(
    const float* __restrict__ x,
    const float* __restrict__ W1, const float* __restrict__ b1,
    const float* __restrict__ W2, const float* __restrict__ b2,
    const float* __restrict__ W3, const float* __restrict__ b3,
    const float* __restrict__ W4, const float* __restrict__ b4)
{
    __shared__ float w1[512], w2[2048];
    __shared__ float sb1[16], sb2[32], sb3[64], sb4[128];
    __shared__ float sin_[832], a1[384], a2[480], a3[128];
    const int tid = threadIdx.x;
    for (int i = tid; i < 512;  i += 256) w1[i] = W1[i];
    for (int i = tid; i < 2048; i += 256) w2[i] = W2[i];
    if (tid < 16)  sb1[tid] = b1[tid];
    if (tid < 32)  sb2[tid] = b2[tid];
    if (tid < 64)  sb3[tid] = b3[tid];
    if (tid < 128) sb4[tid] = b4[tid];

    for (int s = 0; s < 8; s++) {
        const int bt = blockIdx.x * 8 + s;
        __syncthreads();
        for (int i = tid; i < 832; i += 256) sin_[i] = x[(size_t)bt * 832 + i];
        __syncthreads();
        // conv1: (13,8,8)->(6,4,16) k2 s2
        for (int o = tid; o < 384; o += 256) {
            int oh = o >> 6, rem = o & 63, ow = rem >> 4, co = rem & 15;
            float acc = sb1[co];
#pragma unroll
            for (int kh = 0; kh < 2; kh++)
#pragma unroll
                for (int kw = 0; kw < 2; kw++)
#pragma unroll
                    for (int ci = 0; ci < 8; ci++)
                        acc = fmaf(sin_[(oh*2+kh)*64 + (ow*2+kw)*8 + ci],
                                   w1[((kh*2+kw)*8 + ci)*16 + co], acc);
            a1[o] = leaky(acc);
        }
        __syncthreads();
        // conv2: (6,4,16)->(5,3,32) k2 s1
        for (int o = tid; o < 480; o += 256) {
            int oh = o / 96, r2 = o % 96, ow = r2 >> 5, co = r2 & 31;
            float acc = sb2[co];
#pragma unroll
            for (int kh = 0; kh < 2; kh++)
#pragma unroll
                for (int kw = 0; kw < 2; kw++)
#pragma unroll
                    for (int ci = 0; ci < 16; ci++)
                        acc = fmaf(a1[(oh+kh)*64 + (ow+kw)*16 + ci],
                                   w2[((kh*2+kw)*16 + ci)*32 + co], acc);
            a2[o] = leaky(acc);
        }
        __syncthreads();
        // conv3: (5,3,32)->(2,1,64) k2 s2
        for (int o = tid; o < 128; o += 256) {
            int oh = o >> 6, co = o & 63;
            float acc = sb3[co];
#pragma unroll
            for (int kh = 0; kh < 2; kh++)
#pragma unroll
                for (int kw = 0; kw < 2; kw++)
#pragma unroll 8
                    for (int ci = 0; ci < 32; ci++)
                        acc = fmaf(a2[(oh*2+kh)*96 + kw*32 + ci],
                                   __ldg(&W3[((kh*2+kw)*32 + ci)*64 + co]), acc);
            a3[o] = leaky(acc);
        }
        __syncthreads();
        // conv4 1x1 -> (2,1,128); channels_first flatten: feat[c*2 + oh]
        {
            int o = tid, oh = o >> 7, co = o & 127;
            float acc = sb4[co];
#pragma unroll 8
            for (int ci = 0; ci < 64; ci++)
                acc = fmaf(a3[oh*64 + ci], __ldg(&W4[ci*128 + co]), acc);
            g_feat[(size_t)bt * 256 + co*2 + oh] = leaky(acc);
        }
    }
}

// ------------------------------ xz = feat @ Wk + b --------------------------
__global__ __launch_bounds__(128) void xz_kernel(const float* __restrict__ Wk,
                                                 const float* __restrict__ lb)
{
    __shared__ float a_sm[8][256];
    const int tid = threadIdx.x;
    const int r0 = blockIdx.y * 8;
    for (int i = tid; i < 8 * 256; i += 128)
        a_sm[i >> 8][i & 255] = g_feat[(size_t)(r0 + (i >> 8)) * 256 + (i & 255)];
    __syncthreads();

    const int j0 = blockIdx.x * 512 + tid * 4;
    float acc[8][4];
#pragma unroll
    for (int r = 0; r < 8; r++) { acc[r][0]=0.f; acc[r][1]=0.f; acc[r][2]=0.f; acc[r][3]=0.f; }

#pragma unroll 1
    for (int k = 0; k < 256; k += 4) {
        float4 w0 = __ldg((const float4*)(Wk + (size_t)(k+0)*1024 + j0));
        float4 w1 = __ldg((const float4*)(Wk + (size_t)(k+1)*1024 + j0));
        float4 w2 = __ldg((const float4*)(Wk + (size_t)(k+2)*1024 + j0));
        float4 w3 = __ldg((const float4*)(Wk + (size_t)(k+3)*1024 + j0));
#pragma unroll
        for (int r = 0; r < 8; r++) {
            float4 a = *(const float4*)&a_sm[r][k];
            acc[r][0] = fmaf(a.w,w3.x,fmaf(a.z,w2.x,fmaf(a.y,w1.x,fmaf(a.x,w0.x,acc[r][0]))));
            acc[r][1] = fmaf(a.w,w3.y,fmaf(a.z,w2.y,fmaf(a.y,w1.y,fmaf(a.x,w0.y,acc[r][1]))));
            acc[r][2] = fmaf(a.w,w3.z,fmaf(a.z,w2.z,fmaf(a.y,w1.z,fmaf(a.x,w0.z,acc[r][2]))));
            acc[r][3] = fmaf(a.w,w3.w,fmaf(a.z,w2.w,fmaf(a.y,w1.w,fmaf(a.x,w0.w,acc[r][3]))));
        }
    }
    float4 bv = *(const float4*)(lb + j0);
#pragma unroll
    for (int r = 0; r < 8; r++) {
        float4 o; o.x=acc[r][0]+bv.x; o.y=acc[r][1]+bv.y; o.z=acc[r][2]+bv.z; o.w=acc[r][3]+bv.w;
        *(float4*)&g_xz[(size_t)(r0 + r) * 1024 + j0] = o;
    }
}

// ------------------------------ LSTM (persistent, 128 x 256, padded smem) ----
// Bank-conflict-free layout: h rows and weight rows have stride HPAD=260
// floats (260 mod 32 = 4), so the 8 concurrent h-rows per warp land on banks
// {0,4,...,28} and the 8 weight rows on {0,8,16,24}/{4,12,20,28} -- every
// LDS.128 is single-wavefront. Four independent accumulators break chains.
__global__ __launch_bounds__(256) void lstm_kernel(const float* __restrict__ Wr)
{
    extern __shared__ float hstage[];    // 64 rows x HPAD floats
    __shared__ float w_sm[8][HPAD];      // [gate*2+unit][k], padded
    __shared__ float z_sm[64][4][2];
    __shared__ float c_sm[64][2];
    const int tid = threadIdx.x;
    const int j0 = blockIdx.x * 2;

    for (int i = tid; i < 2048; i += 256) {
        int col = i >> 8, k = i & 255, gg = col >> 1, u = col & 1;
        w_sm[col][k] = Wr[(size_t)k * 1024 + gg * 256 + j0 + u];
    }
    if (tid < 128) c_sm[tid >> 1][tid & 1] = 0.f;
    __syncthreads();

    const int b = tid >> 2;   // batch 0..63
    const int g = tid & 3;    // gate 0..3

    const float* hp = hstage + b * HPAD;
    const float* wa = w_sm[g * 2 + 0];
    const float* wb = w_sm[g * 2 + 1];

    for (int t = 0; t < 64; t++) {
        if (t > 0) {
            // stage h(t-1): 4096 float4 across 256 threads, padded rows
            const float4* src = (const float4*)(g_hbuf + ((t - 1) & 1) * (64 * 256));
#pragma unroll
            for (int i = 0; i < 16; i++) {
                int f = tid + i * 256;          // float4 index 0..4095
                int row = f >> 6, k4 = f & 63;  // 64 float4 per row
                float4 v = __ldcg(src + f);
                *(float4*)(hstage + row * HPAD + k4 * 4) = v;
            }
            __syncthreads();
        }
        float a0 = 0.f, a1 = 0.f, b0 = 0.f, b1 = 0.f;
        if (t > 0) {
#pragma unroll 8
            for (int k = 0; k < 256; k += 4) {
                float4 h4 = *(const float4*)(hp + k);
                float4 wA = *(const float4*)(wa + k);
                float4 wB = *(const float4*)(wb + k);
                a0 = fmaf(h4.x, wA.x, a0); a1 = fmaf(h4.y, wA.y, a1);
                b0 = fmaf(h4.x, wB.x, b0); b1 = fmaf(h4.y, wB.y, b1);
                a0 = fmaf(h4.z, wA.z, a0); a1 = fmaf(h4.w, wA.w, a1);
                b0 = fmaf(h4.z, wB.z, b0); b1 = fmaf(h4.w, wB.w, b1);
            }
        }
        const size_t row = (size_t)(b * 64 + t);
        z_sm[b][g][0] = (a0 + a1) + g_xz[row * 1024 + g * 256 + j0];
        z_sm[b][g][1] = (b0 + b1) + g_xz[row * 1024 + g * 256 + j0 + 1];
        __syncthreads();
        if (tid < 128) {
            int b2 = tid >> 1, u = tid & 1;
            float zi = z_sm[b2][0][u], zf = z_sm[b2][1][u];
            float zg = z_sm[b2][2][u], zo = z_sm[b2][3][u];
            float c = sigm(zf) * c_sm[b2][u] + sigm(zi) * tanhf(zg);
            float hv = sigm(zo) * tanhf(c);
            c_sm[b2][u] = c;
            __stcg(&g_hbuf[(t & 1) * (64 * 256) + b2 * 256 + j0 + u], hv);
            g_lstm[(size_t)(b2 * 64 + t) * 256 + j0 + u] = hv;
        }
        grid_barrier_step(gridDim.x, (unsigned int)(t + 1));
    }
}

// ------------------------------ pir head + vpred (smem-staged) ---------------
__global__ __launch_bounds__(256) void pir_v_kernel(
    const float* __restrict__ pirW, const float* __restrict__ pirb,
    const float* __restrict__ vW,  const float* __restrict__ vb,
    const int* __restrict__ a_taken)
{
    __shared__ float ws[256 * 36];
    __shared__ float vws[256];
    __shared__ float hs[8][256];
    const int tid = threadIdx.x, warp = tid >> 5, lane = tid & 31;
    const int r0 = blockIdx.x * 8;

    for (int i = tid; i < 9216; i += 256) ws[i] = pirW[i];
    vws[tid] = vW[tid];
    for (int i = tid; i < 2048; i += 256)
        hs[i >> 8][i & 255] = g_lstm[(size_t)(r0 + (i >> 8)) * 256 + (i & 255)];
    __syncthreads();

    const int i = r0 + warp;
    float acc0 = 0.f, acc1 = 0.f, accv = 0.f;
#pragma unroll 4
    for (int k = 0; k < 256; k++) {
        float hk = hs[warp][k];
        acc0 = fmaf(hk, ws[k * 36 + lane], acc0);
        if (lane < 4) acc1 = fmaf(hk, ws[k * 36 + 32 + lane], acc1);
    }
    for (int k = lane; k < 256; k += 32) accv = fmaf(hs[warp][k], vws[k], accv);

    float l0 = acc0 + __ldg(&pirb[lane]);
    float l1 = (lane < 4) ? acc1 + __ldg(&pirb[lane + 32]) : 0.f;
    float e0 = expf(l0);
    float e1 = (lane < 4) ? expf(l1) : 0.f;
    float cs = e0 + e1;
    float ct = e0 * l0 + ((lane < 4) ? e1 * l1 : 0.f);
#pragma unroll
    for (int o = 16; o > 0; o >>= 1) {
        cs   += __shfl_down_sync(0xffffffffu, cs, o);
        ct   += __shfl_down_sync(0xffffffffu, ct, o);
        accv += __shfl_down_sync(0xffffffffu, accv, o);
    }
    float S = __shfl_sync(0xffffffffu, cs, 0);
    int a = a_taken[i];
    float laA = __shfl_sync(0xffffffffu, l0, a & 31);
    float laB = __shfl_sync(0xffffffffu, l1, a & 31);
    float la = (a < 32) ? laA : laB;
    if (lane == 0) {
        double lS = log((double)S);
        g_ent_pir[i] = (double)ct / (double)S - lS;   // sum p*log p
        g_lg_pir[i]  = (float)((double)la - lS);
        g_vpred[i]   = accv + vb[0];
    }
}

// ------------------------------ pim GEMM + fused epilogue --------------------
__global__ __launch_bounds__(256) void pim_kernel(
    const float* __restrict__ pimW, const float* __restrict__ pimb,
    const int* __restrict__ mask, const int* __restrict__ a_taken)
{
    __shared__ float a_sm[16][256];
    __shared__ float redS[16][8], redT[16][8];
    __shared__ double sRun[16], tRun[16];
    __shared__ float la_sm[16];
    __shared__ int aidx[16];
    const int tid = threadIdx.x, lane = tid & 31, warp = tid >> 5;
    const int r0 = blockIdx.x * 16;

    for (int i = tid; i < 16 * 256; i += 256)
        a_sm[i >> 8][i & 255] = g_lstm[(size_t)(r0 + (i >> 8)) * 256 + (i & 255)];
    if (tid < 16) { sRun[tid] = 0.0; tRun[tid] = 0.0; aidx[tid] = a_taken[r0 + tid]; la_sm[tid] = 0.f; }
    __syncthreads();

#pragma unroll 1
    for (int tile = 0; tile < 4; tile++) {
        const int jb = tile * 1024 + tid * 4;
        const float* Wp = pimW + jb;
        float acc[16][4];
#pragma unroll
        for (int r = 0; r < 16; r++) { acc[r][0]=0.f; acc[r][1]=0.f; acc[r][2]=0.f; acc[r][3]=0.f; }
#pragma unroll 1
        for (int k = 0; k < 256; k += 4) {
            float4 w0 = __ldg((const float4*)(Wp + (size_t)(k+0)*4096));
            float4 w1 = __ldg((const float4*)(Wp + (size_t)(k+1)*4096));
            float4 w2 = __ldg((const float4*)(Wp + (size_t)(k+2)*4096));
            float4 w3 = __ldg((const float4*)(Wp + (size_t)(k+3)*4096));
#pragma unroll
            for (int r = 0; r < 16; r++) {
                float4 a = *(const float4*)&a_sm[r][k];
                acc[r][0] = fmaf(a.w,w3.x,fmaf(a.z,w2.x,fmaf(a.y,w1.x,fmaf(a.x,w0.x,acc[r][0]))));
                acc[r][1] = fmaf(a.w,w3.y,fmaf(a.z,w2.y,fmaf(a.y,w1.y,fmaf(a.x,w0.y,acc[r][1]))));
                acc[r][2] = fmaf(a.w,w3.z,fmaf(a.z,w2.z,fmaf(a.y,w1.z,fmaf(a.x,w0.z,acc[r][2]))));
                acc[r][3] = fmaf(a.w,w3.w,fmaf(a.z,w2.w,fmaf(a.y,w1.w,fmaf(a.x,w0.w,acc[r][3]))));
            }
        }
        float4 bv = __ldg((const float4*)(pimb + jb));
#pragma unroll 1
        for (int r = 0; r < 16; r++) {
            int4 m = *(const int4*)(mask + (size_t)(r0 + r) * 4096 + jb);
            float s = 0.f, t = 0.f, l;
            l = acc[r][0] + bv.x; if (m.x) { float e = expf(l); s += e; t += e * l; } if (jb + 0 == aidx[r]) la_sm[r] = l;
            l = acc[r][1] + bv.y; if (m.y) { float e = expf(l); s += e; t += e * l; } if (jb + 1 == aidx[r]) la_sm[r] = l;
            l = acc[r][2] + bv.z; if (m.z) { float e = expf(l); s += e; t += e * l; } if (jb + 2 == aidx[r]) la_sm[r] = l;
            l = acc[r][3] + bv.w; if (m.w) { float e = expf(l); s += e; t += e * l; } if (jb + 3 == aidx[r]) la_sm[r] = l;
#pragma unroll
            for (int o = 16; o > 0; o >>= 1) {
                s += __shfl_down_sync(0xffffffffu, s, o);
                t += __shfl_down_sync(0xffffffffu, t, o);
            }
            if (lane == 0) { redS[r][warp] = s; redT[r][warp] = t; }
        }
        __syncthreads();
        if (tid < 16) {
            double s = 0.0, t = 0.0;
#pragma unroll
            for (int w = 0; w < 8; w++) { s += (double)redS[tid][w]; t += (double)redT[tid][w]; }
            sRun[tid] += s; tRun[tid] += t;
        }
        __syncthreads();
    }
    if (tid < 16) {
        const int i = r0 + tid;
        double S = sRun[tid], T1 = tRun[tid];
        double lS = log(S);
        g_ent_pim[i] = T1 / S - lS;                      // sum_masked p*log p
        g_lg_pim[i]  = (float)((double)la_sm[tid] - lS); // log pim[i, a]
    }
}

// ------------------------------ vf broadcast (register-tiled) ----------------
__global__ __launch_bounds__(256) void vf_kernel(const float* __restrict__ ovp,
                                                 const float* __restrict__ ret)
{
    __shared__ float vp_s[8];
    __shared__ float part[8][257];
    const int tid = threadIdx.x, warp = tid >> 5, lane = tid & 31;
    const int r0 = blockIdx.x * 8;
    if (tid < 8) vp_s[tid] = g_vpred[r0 + tid];
    __syncthreads();

    float accr[8];
#pragma unroll
    for (int r = 0; r < 8; r++) accr[r] = 0.f;

#pragma unroll 1
    for (int c = 0; c < 4; c++) {
        const int j0 = c * 1024 + tid * 4;
        float4 rt4 = __ldg((const float4*)(ret + j0));
        float4 ov4 = __ldg((const float4*)(ovp + j0));
#pragma unroll
        for (int r = 0; r < 8; r++) {
            float vp = vp_s[r];
            float d, dc, t0, t1, t2, t3;
            d = vp - rt4.x; dc = ov4.x + fminf(fmaxf(vp - ov4.x, -CLIPF), CLIPF) - rt4.x; t0 = fmaxf(d*d, dc*dc);
            d = vp - rt4.y; dc = ov4.y + fminf(fmaxf(vp - ov4.y, -CLIPF), CLIPF) - rt4.y; t1 = fmaxf(d*d, dc*dc);
            d = vp - rt4.z; dc = ov4.z + fminf(fmaxf(vp - ov4.z, -CLIPF), CLIPF) - rt4.z; t2 = fmaxf(d*d, dc*dc);
            d = vp - rt4.w; dc = ov4.w + fminf(fmaxf(vp - ov4.w, -CLIPF), CLIPF) - rt4.w; t3 = fmaxf(d*d, dc*dc);
            accr[r] += (t0 + t1) + (t2 + t3);
        }
    }
#pragma unroll
    for (int r = 0; r < 8; r++) part[r][tid] = accr[r];
    __syncthreads();

    // warp w reduces row w (fixed order -> deterministic)
    double s = 0.0;
#pragma unroll
    for (int m = 0; m < 8; m++) s += (double)part[warp][m * 32 + lane];
#pragma unroll
    for (int o = 16; o > 0; o >>= 1) s += __shfl_down_sync(0xffffffffu, s, o);
    if (lane == 0) g_vf_row[r0 + warp] = s;
}

// ------------------------------ finalize ------------------------------------
__global__ __launch_bounds__(1024) void finalize_kernel(
    const float* __restrict__ GAE, const float* __restrict__ lgold, float* __restrict__ out)
{
    __shared__ double rA[1024], rB[1024];
    const int tid = threadIdx.x;
    double s1 = 0.0, s2 = 0.0;
    for (int i = tid; i < BT; i += 1024) { double g = GAE[i]; s1 += g; s2 += g * g; }
    rA[tid] = s1; rB[tid] = s2; __syncthreads();
    for (int o = 512; o > 0; o >>= 1) {
        if (tid < o) { rA[tid] += rA[tid + o]; rB[tid] += rB[tid + o]; }
        __syncthreads();
    }
    double mean = rA[0] / (double)BT;
    double var  = rB[0] / (double)BT - mean * mean;
    if (var < 0.0) var = 0.0;
    double denom = sqrt(var) + 1e-8;
    __syncthreads();

    double pg = 0.0, ent = 0.0, vf = 0.0;
    for (int i = tid; i < BT; i += 1024) {
        double g = ((double)GAE[i] - mean) / denom;
        float lgnew = ((i & 1) == 0) ? g_lg_pir[i] : g_lg_pim[i];
        double rt = exp((double)lgnew - (double)lgold[i]);
        double rtc = rt < (1.0 - CLIPF) ? (1.0 - CLIPF) : (rt > (1.0 + CLIPF) ? (1.0 + CLIPF) : rt);
        double p1 = -g * rt, p2 = -g * rtc;
        pg  += (p1 > p2) ? p1 : p2;
        ent += g_ent_pir[i] + g_ent_pim[i];
        vf  += g_vf_row[i];
    }
    rA[tid] = pg; rB[tid] = ent; __syncthreads();
    for (int o = 512; o > 0; o >>= 1) {
        if (tid < o) { rA[tid] += rA[tid + o]; rB[tid] += rB[tid + o]; }
        __syncthreads();
    }
    double pg_tot = rA[0], ent_tot = rB[0];
    __syncthreads();
    rA[tid] = vf; __syncthreads();
    for (int o = 512; o > 0; o >>= 1) {
        if (tid < o) rA[tid] += rA[tid + o];
        __syncthreads();
    }
    if (tid == 0) {
        double pg_loss = pg_tot / (double)BT;
        double entropy = -ent_tot;
        double vf_loss = 0.5 * rA[0] / ((double)BT * (double)BT);
        out[0] = (float)(pg_loss - entropy + vf_loss);
        out[1] = (float)pg_loss;
        out[2] = (float)entropy;
        out[3] = (float)vf_loss;
    }
}

// ------------------------------ launch --------------------------------------
extern "C" void kernel_launch(void* const* d_in, const int* in_sizes, int n_in,
                              void* d_out, int out_size) {
    const float* x      = (const float*)d_in[0];
    const int*   mask   = (const int*)  d_in[1];
    const float* lgold  = (const float*)d_in[2];
    const int*   ataken = (const int*)  d_in[3];
    const float* GAE    = (const float*)d_in[4];
    const float* ovp    = (const float*)d_in[5];
    const float* ret    = (const float*)d_in[6];
    const float* W1 = (const float*)d_in[7],  *b1 = (const float*)d_in[8];
    const float* W2 = (const float*)d_in[9],  *b2 = (const float*)d_in[10];
    const float* W3 = (const float*)d_in[11], *b3 = (const float*)d_in[12];
    const float* W4 = (const float*)d_in[13], *b4 = (const float*)d_in[14];
    const float* lk = (const float*)d_in[15];
    const float* lr = (const float*)d_in[16];
    const float* lb = (const float*)d_in[17];
    const float* pirW = (const float*)d_in[18], *pirb = (const float*)d_in[19];
    const float* pimW = (const float*)d_in[20], *pimb = (const float*)d_in[21];
    const float* vW   = (const float*)d_in[22], *vb   = (const float*)d_in[23];
    float* out = (float*)d_out;

    const int lstm_smem = 64 * HPAD * 4;   // 66560 B
    static int lstm_smem_set = 0;
    if (!lstm_smem_set) {
        cudaFuncSetAttribute(lstm_kernel,
                             cudaFuncAttributeMaxDynamicSharedMemorySize, lstm_smem);
        lstm_smem_set = 1;
    }

    init_kernel<<<1, 1>>>();
    conv_kernel<<<512, 256>>>(x, W1, b1, W2, b2, W3, b3, W4, b4);
    xz_kernel<<<dim3(2, 512), 128>>>(lk, lb);
    lstm_kernel<<<128, 256, lstm_smem>>>(lr);
    pir_v_kernel<<<512, 256>>>(pirW, pirb, vW, vb, ataken);
    pim_kernel<<<256, 256>>>(pimW, pimb, mask, ataken);
    vf_kernel<<<512, 256>>>(ovp, ret);
    finalize_kernel<<<1, 1024>>>(GAE, lgold, out);
}